// round 11
// baseline (speedup 1.0000x reference)
#include <cuda_runtime.h>
#include <cuda_bf16.h>
#include <cstdint>

#define T 256
#define H 1024
#define E 64
#define IDIM 512
#define SI 2048
#define TOPK 6

// ---------------- device scratch ----------------
__device__ int   g_cnt[E];
__device__ int   g_slot[E * T];
__device__ int   g_tok[E * T];
__device__ float g_wt[E * T];
__device__ float g_act[T * TOPK * IDIM];   // 3 MB
__device__ float g_eo[T * TOPK * H];       // 6 MB
__device__ float g_sact[T * SI];           // 2 MB

__device__ __forceinline__ float silu(float v) { return v / (1.0f + expf(-v)); }

// ---------------- init ----------------
__global__ void init_kernel() {
    if (threadIdx.x < E) g_cnt[threadIdx.x] = 0;
}

// ---------------- gate + routing: one block per token ----------------
__global__ void gate_routing_kernel(const float* __restrict__ x,
                                    const float* __restrict__ gw,
                                    const float* __restrict__ ebias) {
    __shared__ float xs[H];
    __shared__ float part[256];
    __shared__ float logits[E];
    int t = blockIdx.x, tid = threadIdx.x;

    ((float4*)xs)[tid] = ((const float4*)(x + (size_t)t * H))[tid];
    __syncthreads();

    int e = tid >> 2, q = tid & 3;
    const float* gr = gw + (size_t)e * H + q * 256;
    const float* xr = xs + q * 256;
    float s = 0.0f;
#pragma unroll 8
    for (int k = 0; k < 256; k += 4) {
        float4 g = *(const float4*)(gr + k);
        float4 xv = *(const float4*)(xr + k);
        s += g.x * xv.x + g.y * xv.y + g.z * xv.z + g.w * xv.w;
    }
    part[tid] = s;
    __syncthreads();
    if (tid < E) logits[tid] = part[tid * 4] + part[tid * 4 + 1] + part[tid * 4 + 2] + part[tid * 4 + 3];
    __syncthreads();

    if (tid == 0) {
        float sc[E], swb[E];
        for (int i = 0; i < E; i++) {
            float l = logits[i];
            sc[i] = 1.0f / (1.0f + expf(-l));
            swb[i] = sc[i] + ebias[i];
        }
        float gs[8];
        for (int g = 0; g < 8; g++) {
            float m1 = -1e30f, m2 = -1e30f;
            for (int j = 0; j < 8; j++) {
                float v = swb[g * 8 + j];
                if (v > m1) { m2 = m1; m1 = v; }
                else if (v > m2) { m2 = v; }
            }
            gs[g] = m1 + m2;
        }
        bool gsel[8];
        for (int g = 0; g < 8; g++) gsel[g] = false;
        for (int r = 0; r < 4; r++) {
            int best = 0; float bv = -1e30f;
            for (int g = 0; g < 8; g++)
                if (!gsel[g] && gs[g] > bv) { bv = gs[g]; best = g; }
            gsel[best] = true;
        }
        bool picked[E];
        for (int i = 0; i < E; i++) picked[i] = false;
        int idx[TOPK];
        float wsum = 0.0f;
        for (int r = 0; r < TOPK; r++) {
            int best = 0; float bv = -1e30f;
            for (int i = 0; i < E; i++) {
                if (picked[i]) continue;
                float v = gsel[i >> 3] ? swb[i] : 0.0f;
                if (v > bv) { bv = v; best = i; }
            }
            picked[best] = true;
            idx[r] = best;
            wsum += sc[best];
        }
        float inv = 2.5f / (wsum + 1e-20f);
        for (int r = 0; r < TOPK; r++) {
            int ee = idx[r];
            int pos = atomicAdd(&g_cnt[ee], 1);
            g_slot[ee * T + pos] = t * TOPK + r;
            g_tok[ee * T + pos] = t;
            g_wt[ee * T + pos] = sc[ee] * inv;
        }
    }
}

// ========== bf16-split MMA GEMM: M64 x N64, 8 warps ==========
// C[64, 64] = A[64, KD] * B[64, KD]^T.
// B: fp32 LDG (2-chunk-deep register prefetch) -> bf16 hi/lo split -> STS
//    (stride-40 rows, R4-verified) -> LDSM fragments.
// A: register-direct fragment LDG (R7-verified), hi/lo split in registers.
// 3-term MMA: hh + hl + lh. Warp (wm in 0..3, wn in 0..1) owns m16 x n32.

__device__ __forceinline__ void mma_bf16(float c[4], const unsigned a[4],
                                         unsigned b0, unsigned b1) {
    asm("mma.sync.aligned.m16n8k16.row.col.f32.bf16.bf16.f32 "
        "{%0,%1,%2,%3}, {%4,%5,%6,%7}, {%8,%9}, {%0,%1,%2,%3};"
        : "+f"(c[0]), "+f"(c[1]), "+f"(c[2]), "+f"(c[3])
        : "r"(a[0]), "r"(a[1]), "r"(a[2]), "r"(a[3]), "r"(b0), "r"(b1));
}

__device__ __forceinline__ void ldsm4(unsigned r[4], unsigned addr) {
    asm volatile("ldmatrix.sync.aligned.m8n8.x4.shared.b16 {%0,%1,%2,%3}, [%4];"
        : "=r"(r[0]), "=r"(r[1]), "=r"(r[2]), "=r"(r[3]) : "r"(addr));
}

__device__ __forceinline__ void split_pair(float2 v, unsigned &hi, unsigned &lo) {
    unsigned ux = __float_as_uint(v.x), uy = __float_as_uint(v.y);
    float lx = v.x - __uint_as_float(ux & 0xffff0000u);
    float ly = v.y - __uint_as_float(uy & 0xffff0000u);
    asm("prmt.b32 %0, %1, %2, 0x7632;" : "=r"(hi) : "r"(ux), "r"(uy));
    __nv_bfloat162 l2 = __floats2bfloat162_rn(lx, ly);
    lo = *reinterpret_cast<unsigned*>(&l2);
}

// convert float4 -> 4 bf16 hi (8B) + 4 bf16 lo (8B), packed stores
__device__ __forceinline__ void cvt_store(float4 v, __nv_bfloat16* hi, __nv_bfloat16* lo) {
    unsigned h01, l01, h23, l23;
    split_pair(make_float2(v.x, v.y), h01, l01);
    split_pair(make_float2(v.z, v.w), h23, l23);
    *(uint2*)hi = make_uint2(h01, h23);
    *(uint2*)lo = make_uint2(l01, l23);
}

// smem: B planes only: [buf][NB][plane(hi/lo)][64 rows * 40 bf16]
#define BPLANE 2560

// EPI: 0 = silu(acc0)*acc1   1 = acc0 * combine_weight   2 = plain acc0
template<int KD, bool TWOB, int EPI, bool GATHER, bool ATOK, int ASRC, int ODST>
__device__ __forceinline__ void gemm_body(
    int bx, int by, int bz,
    const float* __restrict__ Ain, const float* __restrict__ B1in,
    const float* __restrict__ B2in, float* __restrict__ Oout,
    int ostride, long estrideB, __nv_bfloat16* sB)
{
    constexpr int NB = TWOB ? 2 : 1;
    constexpr int NCH = KD / 32;

    const float* A = (ASRC == 0) ? Ain : (ASRC == 1) ? (const float*)g_act : (const float*)g_sact;
    float* O = (ODST == 0) ? Oout : (ODST == 1) ? g_act : (ODST == 2) ? g_eo : g_sact;

    int tid = threadIdx.x, lane = tid & 31, wid = tid >> 5;
    int wm = wid & 3, wn = wid >> 2;
    int n0 = bx * 64;

    __shared__ int s_row[64];
    __shared__ int s_orow[64];
    __shared__ float s_wt[64];

    int mcnt = 64;
    const float* Bp[NB];
    if (GATHER) {
        int e = by;
        int n = g_cnt[e];
        int m0 = bz * 64;
        if (m0 >= n) return;
        mcnt = min(64, n - m0);
        if (tid < 64) {
            bool v = tid < mcnt;
            int idx = e * T + m0 + tid;
            s_row[tid]  = v ? (ATOK ? g_tok[idx] : g_slot[idx]) : 0;
            s_orow[tid] = v ? g_slot[idx] : 0;
            s_wt[tid]   = v ? g_wt[idx] : 0.0f;
        }
        Bp[0] = B1in + (size_t)e * estrideB + (size_t)n0 * KD;
        if (TWOB) Bp[1] = B2in + (size_t)e * estrideB + (size_t)n0 * KD;
    } else {
        int m0 = by * 64;
        if (tid < 64) { s_row[tid] = m0 + tid; s_orow[tid] = m0 + tid; }
        Bp[0] = B1in + (size_t)n0 * KD;
        if (TWOB) Bp[1] = B2in + (size_t)n0 * KD;
    }
    __syncthreads();

    int g = lane >> 2, c0 = (lane & 3) * 2;

    // A: register-direct fragment pointers (rows wm*16+g, wm*16+g+8)
    const float* pa0 = A + (size_t)s_row[wm * 16 + g] * KD + c0;
    const float* pa1 = A + (size_t)s_row[wm * 16 + g + 8] * KD + c0;

    // B staging mapping: per matrix, 512 float4 per k32 chunk; 256 threads x2
    // idx = tid + l*256: row = idx>>3, kq = idx&7 (float4 col)
    int r0 = tid >> 3, kq = tid & 7;           // l=0
    int r1 = (tid + 256) >> 3;                 // l=1 (same kq)

    float4 pb[2][NB][2];                       // [regbuf][matrix][l]
    auto load_B = [&](int buf, int ch) {
        int k0 = ch * 32 + kq * 4;
#pragma unroll
        for (int m = 0; m < NB; m++) {
            pb[buf][m][0] = *(const float4*)&Bp[m][(size_t)r0 * KD + k0];
            pb[buf][m][1] = *(const float4*)&Bp[m][(size_t)r1 * KD + k0];
        }
    };
    auto store_B = [&](int sbuf, int buf) {
#pragma unroll
        for (int m = 0; m < NB; m++) {
            __nv_bfloat16* hiP = sB + ((sbuf * NB + m) * 2 + 0) * BPLANE;
            __nv_bfloat16* loP = sB + ((sbuf * NB + m) * 2 + 1) * BPLANE;
            cvt_store(pb[buf][m][0], hiP + r0 * 40 + kq * 4, loP + r0 * 40 + kq * 4);
            cvt_store(pb[buf][m][1], hiP + r1 * 40 + kq * 4, loP + r1 * 40 + kq * 4);
        }
    };

    // A register double-buffer: 8 float2 per chunk (R7-verified order)
    float2 fa[2][8];
    auto load_A = [&](int buf, int ch) {
        int k = ch * 32;
#pragma unroll
        for (int s = 0; s < 2; s++) {
            fa[buf][s * 4 + 0] = *(const float2*)(pa0 + k + s * 16);
            fa[buf][s * 4 + 1] = *(const float2*)(pa1 + k + s * 16);
            fa[buf][s * 4 + 2] = *(const float2*)(pa0 + k + s * 16 + 8);
            fa[buf][s * 4 + 3] = *(const float2*)(pa1 + k + s * 16 + 8);
        }
    };

    float acc[NB][4][4];
#pragma unroll
    for (int m = 0; m < NB; m++)
#pragma unroll
        for (int nt = 0; nt < 4; nt++)
#pragma unroll
            for (int j = 0; j < 4; j++) acc[m][nt][j] = 0.0f;

    unsigned bSm = (unsigned)__cvta_generic_to_shared(sB);
    int brow_base = wn * 32 + (lane & 7) + ((lane & 16) >> 1);
    int bcol_off = (lane & 8);

    auto compute = [&](int sbuf, int abuf) {
#pragma unroll
        for (int s = 0; s < 2; s++) {
            unsigned ah[4], al[4];
#pragma unroll
            for (int i = 0; i < 4; i++) split_pair(fa[abuf][s * 4 + i], ah[i], al[i]);
#pragma unroll
            for (int m = 0; m < NB; m++) {
                unsigned bHi = bSm + (unsigned)(((sbuf * NB + m) * 2) * BPLANE * 2);
                unsigned bLo = bHi + BPLANE * 2;
                int o0 = (brow_base * 40 + s * 16 + bcol_off) * 2;
                int o1 = ((brow_base + 16) * 40 + s * 16 + bcol_off) * 2;
                unsigned bh[8], bl[8];
                ldsm4(bh, bHi + o0); ldsm4(bh + 4, bHi + o1);
                ldsm4(bl, bLo + o0); ldsm4(bl + 4, bLo + o1);
#pragma unroll
                for (int nt = 0; nt < 4; nt++) {
                    mma_bf16(acc[m][nt], ah, bh[nt * 2], bh[nt * 2 + 1]);
                    mma_bf16(acc[m][nt], ah, bl[nt * 2], bl[nt * 2 + 1]);
                    mma_bf16(acc[m][nt], al, bh[nt * 2], bh[nt * 2 + 1]);
                }
            }
        }
    };

    // pipeline: B regs 2 chunks deep, smem double-buffered, A regs 1 deep
    load_B(0, 0);
    if (NCH > 1) load_B(1, 1);
    load_A(0, 0);
    store_B(0, 0);
    __syncthreads();

#pragma unroll 1
    for (int ch = 0; ch < NCH; ch++) {
        if (ch + 2 < NCH) load_B(ch & 1, ch + 2);
        if (ch + 1 < NCH) load_A((ch + 1) & 1, ch + 1);
        compute(ch & 1, ch & 1);
        if (ch + 1 < NCH) {
            store_B((ch + 1) & 1, (ch + 1) & 1);
            __syncthreads();
        }
    }

    // epilogue (R4-verified layout)
    int tq = lane & 3;
#pragma unroll
    for (int half = 0; half < 2; half++) {
        int m = wm * 16 + g + half * 8;
        if (m >= mcnt) continue;
        float w = (EPI == 1) ? s_wt[m] : 0.0f;
        float* op = O + (size_t)s_orow[m] * ostride + n0 + wn * 32 + 2 * tq;
#pragma unroll
        for (int nt = 0; nt < 4; nt++) {
            float v0, v1;
            if (EPI == 0) {
                v0 = silu(acc[0][nt][half * 2])     * acc[1][nt][half * 2];
                v1 = silu(acc[0][nt][half * 2 + 1]) * acc[1][nt][half * 2 + 1];
            } else if (EPI == 1) {
                v0 = acc[0][nt][half * 2] * w;
                v1 = acc[0][nt][half * 2 + 1] * w;
            } else {
                v0 = acc[0][nt][half * 2];
                v1 = acc[0][nt][half * 2 + 1];
            }
            *(float2*)&op[nt * 8] = make_float2(v0, v1);
        }
    }
}

// ---- K1: sharedUp (128 blocks) + routed stageA (2048 blocks) ----
#define K1_SHARED 128
#define K1_TOTAL (K1_SHARED + 8 * 64 * 4)
#define K1_SMEM (2 * 2 * 2 * BPLANE * 2)     // 40960
__global__ __launch_bounds__(256) void k1_kernel(
    const float* __restrict__ x, const float* __restrict__ w1,
    const float* __restrict__ w3, const float* __restrict__ wsg,
    const float* __restrict__ wsu)
{
    extern __shared__ __nv_bfloat16 sB[];
    int id = blockIdx.x;
    if (id < K1_SHARED) {
        // sact = silu(x @ wsg^T) * (x @ wsu^T)   [32 n-tiles x 4 m-tiles]
        gemm_body<1024, true, 0, false, false, 0, 3>(
            id & 31, id >> 5, 0, x, wsg, wsu, nullptr, SI, 0, sB);
    } else {
        int rid = id - K1_SHARED;
        // act = silu(x_e @ w1^T) * (x_e @ w3^T)  [gather tokens]
        gemm_body<1024, true, 0, true, true, 0, 1>(
            rid & 7, (rid >> 3) & 63, rid >> 9, x, w1, w3, nullptr,
            IDIM, (long)IDIM * H, sB);
    }
}

// ---- K2: sharedDown (64 blocks) + routed stageB (4096 blocks) ----
#define K2_SHARED 64
#define K2_TOTAL (K2_SHARED + 16 * 64 * 4)
#define K2_SMEM (2 * 1 * 2 * BPLANE * 2)     // 20480
__global__ __launch_bounds__(256) void k2_kernel(
    const float* __restrict__ w2, const float* __restrict__ wsd,
    float* __restrict__ out)
{
    extern __shared__ __nv_bfloat16 sB[];
    int id = blockIdx.x;
    if (id < K2_SHARED) {
        // out = sact @ wsd^T   [16 n-tiles x 4 m-tiles]
        gemm_body<2048, false, 2, false, false, 2, 0>(
            id & 15, id >> 4, 0, nullptr, wsd, wsd, out, H, 0, sB);
    } else {
        int rid = id - K2_SHARED;
        // eo = (act_e @ w2^T) * cw  [gather slots]
        gemm_body<512, false, 1, true, false, 1, 2>(
            rid & 15, (rid >> 4) & 63, rid >> 10, nullptr, w2, w2, nullptr,
            H, (long)H * IDIM, sB);
    }
}

// ---- combine: out += sum of the 6 weighted expert outputs per token ----
__global__ void combine_kernel(float* __restrict__ out) {
    int idx = blockIdx.x * 256 + threadIdx.x;
    int t = idx >> 10;
    int h = idx & 1023;
    float s = out[idx];
#pragma unroll
    for (int k = 0; k < TOPK; k++)
        s += g_eo[((size_t)(t * TOPK + k) << 10) + h];
    out[idx] = s;
}

// ---------------- launch ----------------
extern "C" void kernel_launch(void* const* d_in, const int* in_sizes, int n_in,
                              void* d_out, int out_size) {
    const float* x     = (const float*)d_in[0];
    const float* gw    = (const float*)d_in[1];
    const float* ebias = (const float*)d_in[2];
    const float* w1    = (const float*)d_in[3];
    const float* w3    = (const float*)d_in[4];
    const float* w2    = (const float*)d_in[5];
    const float* wsg   = (const float*)d_in[6];
    const float* wsu   = (const float*)d_in[7];
    const float* wsd   = (const float*)d_in[8];
    float* out = (float*)d_out;

    cudaFuncSetAttribute(k1_kernel, cudaFuncAttributeMaxDynamicSharedMemorySize, K1_SMEM);
    cudaFuncSetAttribute(k2_kernel, cudaFuncAttributeMaxDynamicSharedMemorySize, K2_SMEM);

    init_kernel<<<1, 64>>>();
    gate_routing_kernel<<<T, 256>>>(x, gw, ebias);
    k1_kernel<<<K1_TOTAL, 256, K1_SMEM>>>(x, w1, w3, wsg, wsu);
    k2_kernel<<<K2_TOTAL, 256, K2_SMEM>>>(w2, wsd, out);
    combine_kernel<<<(T * H) / 256, 256>>>(out);
}

// round 12
// speedup vs baseline: 1.0027x; 1.0027x over previous
#include <cuda_runtime.h>
#include <cuda_bf16.h>
#include <cstdint>

#define T 256
#define H 1024
#define E 64
#define IDIM 512
#define SI 2048
#define TOPK 6

// ---------------- device scratch ----------------
__device__ int   g_cnt[E];
__device__ int   g_slot[E * T];
__device__ int   g_tok[E * T];
__device__ float g_wt[E * T];
__device__ float g_act[T * TOPK * IDIM];   // 3 MB
__device__ float g_eo[T * TOPK * H];       // 6 MB
__device__ float g_sact[T * SI];           // 2 MB

__device__ __forceinline__ float silu(float v) { return v / (1.0f + expf(-v)); }

// ---------------- init ----------------
__global__ void init_kernel() {
    if (threadIdx.x < E) g_cnt[threadIdx.x] = 0;
}

// ---------------- gate + routing: one block per token ----------------
__global__ void gate_routing_kernel(const float* __restrict__ x,
                                    const float* __restrict__ gw,
                                    const float* __restrict__ ebias) {
    __shared__ float xs[H];
    __shared__ float part[256];
    __shared__ float logits[E];
    int t = blockIdx.x, tid = threadIdx.x;

    ((float4*)xs)[tid] = ((const float4*)(x + (size_t)t * H))[tid];
    __syncthreads();

    int e = tid >> 2, q = tid & 3;
    const float* gr = gw + (size_t)e * H + q * 256;
    const float* xr = xs + q * 256;
    float s = 0.0f;
#pragma unroll 8
    for (int k = 0; k < 256; k += 4) {
        float4 g = *(const float4*)(gr + k);
        float4 xv = *(const float4*)(xr + k);
        s += g.x * xv.x + g.y * xv.y + g.z * xv.z + g.w * xv.w;
    }
    part[tid] = s;
    __syncthreads();
    if (tid < E) logits[tid] = part[tid * 4] + part[tid * 4 + 1] + part[tid * 4 + 2] + part[tid * 4 + 3];
    __syncthreads();

    if (tid == 0) {
        float sc[E], swb[E];
        for (int i = 0; i < E; i++) {
            float l = logits[i];
            sc[i] = 1.0f / (1.0f + expf(-l));
            swb[i] = sc[i] + ebias[i];
        }
        float gs[8];
        for (int g = 0; g < 8; g++) {
            float m1 = -1e30f, m2 = -1e30f;
            for (int j = 0; j < 8; j++) {
                float v = swb[g * 8 + j];
                if (v > m1) { m2 = m1; m1 = v; }
                else if (v > m2) { m2 = v; }
            }
            gs[g] = m1 + m2;
        }
        bool gsel[8];
        for (int g = 0; g < 8; g++) gsel[g] = false;
        for (int r = 0; r < 4; r++) {
            int best = 0; float bv = -1e30f;
            for (int g = 0; g < 8; g++)
                if (!gsel[g] && gs[g] > bv) { bv = gs[g]; best = g; }
            gsel[best] = true;
        }
        bool picked[E];
        for (int i = 0; i < E; i++) picked[i] = false;
        int idx[TOPK];
        float wsum = 0.0f;
        for (int r = 0; r < TOPK; r++) {
            int best = 0; float bv = -1e30f;
            for (int i = 0; i < E; i++) {
                if (picked[i]) continue;
                float v = gsel[i >> 3] ? swb[i] : 0.0f;
                if (v > bv) { bv = v; best = i; }
            }
            picked[best] = true;
            idx[r] = best;
            wsum += sc[best];
        }
        float inv = 2.5f / (wsum + 1e-20f);
        for (int r = 0; r < TOPK; r++) {
            int ee = idx[r];
            int pos = atomicAdd(&g_cnt[ee], 1);
            g_slot[ee * T + pos] = t * TOPK + r;
            g_tok[ee * T + pos] = t;
            g_wt[ee * T + pos] = sc[ee] * inv;
        }
    }
}

// ================= bf16-split MMA GEMM (R4 champion + pipeline upgrades) ====
// C[M=32, N=64] = A[32, KD] * B[N, KD]^T. fp32 -> bf16 hi/lo in smem,
// 3-term MMA (hh + hl + lh). 128 threads = 4 warps, warp (wm, wn) = m16 x n32.
// Upgrades vs R4: packed uint2 STS; 2-chunk-deep LDG register prefetch.

__device__ __forceinline__ void ldsm4(unsigned r[4], unsigned addr) {
    asm volatile("ldmatrix.sync.aligned.m8n8.x4.shared.b16 {%0,%1,%2,%3}, [%4];"
        : "=r"(r[0]), "=r"(r[1]), "=r"(r[2]), "=r"(r[3]) : "r"(addr));
}

__device__ __forceinline__ void mma_bf16(float c[4], const unsigned a[4],
                                         unsigned b0, unsigned b1) {
    asm("mma.sync.aligned.m16n8k16.row.col.f32.bf16.bf16.f32 "
        "{%0,%1,%2,%3}, {%4,%5,%6,%7}, {%8,%9}, {%0,%1,%2,%3};"
        : "+f"(c[0]), "+f"(c[1]), "+f"(c[2]), "+f"(c[3])
        : "r"(a[0]), "r"(a[1]), "r"(a[2]), "r"(a[3]), "r"(b0), "r"(b1));
}

__device__ __forceinline__ void split_pair(float2 v, unsigned &hi, unsigned &lo) {
    unsigned ux = __float_as_uint(v.x), uy = __float_as_uint(v.y);
    float lx = v.x - __uint_as_float(ux & 0xffff0000u);
    float ly = v.y - __uint_as_float(uy & 0xffff0000u);
    asm("prmt.b32 %0, %1, %2, 0x7632;" : "=r"(hi) : "r"(ux), "r"(uy));
    __nv_bfloat162 l2 = __floats2bfloat162_rn(lx, ly);
    lo = *reinterpret_cast<unsigned*>(&l2);
}

// float4 -> 4 bf16 hi (one 8B store) + 4 bf16 lo (one 8B store)
__device__ __forceinline__ void cvt_store(float4 v, __nv_bfloat16* hi, __nv_bfloat16* lo) {
    unsigned h01, l01, h23, l23;
    split_pair(make_float2(v.x, v.y), h01, l01);
    split_pair(make_float2(v.z, v.w), h23, l23);
    *(uint2*)hi = make_uint2(h01, h23);
    *(uint2*)lo = make_uint2(l01, l23);
}

// smem element layout (bf16 counts):
//   sA: [2 buf][2 plane][32*40]      sB: [2 buf][NB][2 plane][64*40]
#define APLANE 1280
#define BPLANE 2560

// EPI: 0 = silu(acc0)*acc1   1 = acc0 * combine_weight   2 = plain acc0
template<int KD, bool TWOB, int EPI, bool GATHER, bool ATOK, int ASRC, int ODST>
__device__ __forceinline__ void gemm_body(
    int bx, int by, int bz,
    const float* __restrict__ Ain, const float* __restrict__ B1in,
    const float* __restrict__ B2in, float* __restrict__ Oout,
    int ostride, long estrideB, char* dynsmem)
{
    constexpr int NB = TWOB ? 2 : 1;
    constexpr int NCH = KD / 32;

    const float* A = (ASRC == 0) ? Ain : (ASRC == 1) ? (const float*)g_act : (const float*)g_sact;
    float* O = (ODST == 0) ? Oout : (ODST == 1) ? g_act : (ODST == 2) ? g_eo : g_sact;

    int tid = threadIdx.x, lane = tid & 31, wid = tid >> 5;
    int wm = wid & 1, wn = wid >> 1;
    int n0 = bx * 64;

    __nv_bfloat16* sA = (__nv_bfloat16*)dynsmem;
    __nv_bfloat16* sB = sA + 2 * 2 * APLANE;

    __shared__ int s_row[32];
    __shared__ int s_orow[32];
    __shared__ float s_wt[32];

    int mcnt = 32;
    const float* Bp[NB];
    if (GATHER) {
        int e = by;
        int n = g_cnt[e];
        int m0 = bz * 32;
        if (m0 >= n) return;
        mcnt = min(32, n - m0);
        if (tid < 32) {
            bool v = tid < mcnt;
            int idx = e * T + m0 + tid;
            s_row[tid]  = v ? (ATOK ? g_tok[idx] : g_slot[idx]) : -1;
            s_orow[tid] = v ? g_slot[idx] : 0;
            s_wt[tid]   = v ? g_wt[idx] : 0.0f;
        }
        Bp[0] = B1in + (size_t)e * estrideB + (size_t)n0 * KD;
        if (TWOB) Bp[1] = B2in + (size_t)e * estrideB + (size_t)n0 * KD;
    } else {
        int m0 = by * 32;
        if (tid < 32) { s_row[tid] = m0 + tid; s_orow[tid] = m0 + tid; }
        Bp[0] = B1in + (size_t)n0 * KD;
        if (TWOB) Bp[1] = B2in + (size_t)n0 * KD;
    }
    __syncthreads();

    // staging lane mapping (R4-verified)
    int ar = tid >> 2, ac = (tid & 3) * 2;   // A: row ar, float4 cols ac, ac+1
    int br = tid >> 1, bc = (tid & 1) * 4;   // B: row br, float4 cols bc..bc+3
    long aoff = (long)s_row[ar];

    // 2-deep register prefetch
    float4 pa[2][2];
    float4 pb[2][NB][4];

    auto load_chunk = [&](int rbuf, int kt) {
#pragma unroll
        for (int i = 0; i < 2; i++) {
            if (!GATHER || aoff >= 0)
                pa[rbuf][i] = *(const float4*)&A[(size_t)aoff * KD + kt + (ac + i) * 4];
            else
                pa[rbuf][i] = make_float4(0.f, 0.f, 0.f, 0.f);
        }
#pragma unroll
        for (int m = 0; m < NB; m++)
#pragma unroll
            for (int i = 0; i < 4; i++)
                pb[rbuf][m][i] = *(const float4*)&Bp[m][(size_t)br * KD + kt + (bc + i) * 4];
    };

    auto store_chunk = [&](int sbuf, int rbuf) {
#pragma unroll
        for (int i = 0; i < 2; i++)
            cvt_store(pa[rbuf][i],
                &sA[(sbuf * 2 + 0) * APLANE + ar * 40 + (ac + i) * 4],
                &sA[(sbuf * 2 + 1) * APLANE + ar * 40 + (ac + i) * 4]);
#pragma unroll
        for (int m = 0; m < NB; m++)
#pragma unroll
            for (int i = 0; i < 4; i++)
                cvt_store(pb[rbuf][m][i],
                    &sB[((sbuf * NB + m) * 2 + 0) * BPLANE + br * 40 + (bc + i) * 4],
                    &sB[((sbuf * NB + m) * 2 + 1) * BPLANE + br * 40 + (bc + i) * 4]);
    };

    float acc[NB][4][4];
#pragma unroll
    for (int m = 0; m < NB; m++)
#pragma unroll
        for (int nt = 0; nt < 4; nt++)
#pragma unroll
            for (int j = 0; j < 4; j++) acc[m][nt][j] = 0.0f;

    unsigned aSm = (unsigned)__cvta_generic_to_shared(sA);
    unsigned bSm = (unsigned)__cvta_generic_to_shared(sB);
    int arow_off = ((wm * 16 + (lane & 15)) * 40 + ((lane >> 4) & 1) * 8) * 2;
    int brow_base = wn * 32 + (lane & 7) + ((lane & 16) >> 1);
    int bcol_off = (lane & 8);

    auto compute = [&](int sbuf) {
        unsigned aHi = aSm + (unsigned)(sbuf * 2 * APLANE * 2);
        unsigned aLo = aHi + APLANE * 2;
#pragma unroll
        for (int s = 0; s < 2; s++) {
            unsigned ah[4], al[4];
            ldsm4(ah, aHi + arow_off + s * 32);
            ldsm4(al, aLo + arow_off + s * 32);
#pragma unroll
            for (int m = 0; m < NB; m++) {
                unsigned bHi = bSm + (unsigned)(((sbuf * NB + m) * 2) * BPLANE * 2);
                unsigned bLo = bHi + BPLANE * 2;
                int o0 = (brow_base * 40 + s * 16 + bcol_off) * 2;
                int o1 = ((brow_base + 16) * 40 + s * 16 + bcol_off) * 2;
                unsigned bh[8], bl[8];
                ldsm4(bh, bHi + o0); ldsm4(bh + 4, bHi + o1);
                ldsm4(bl, bLo + o0); ldsm4(bl + 4, bLo + o1);
#pragma unroll
                for (int nt = 0; nt < 4; nt++) {
                    mma_bf16(acc[m][nt], ah, bh[nt * 2], bh[nt * 2 + 1]);
                    mma_bf16(acc[m][nt], ah, bl[nt * 2], bl[nt * 2 + 1]);
                    mma_bf16(acc[m][nt], al, bh[nt * 2], bh[nt * 2 + 1]);
                }
            }
        }
    };

    // pipeline: reg prefetch 2 deep, smem double-buffered, 1 barrier/chunk
    load_chunk(0, 0);
    load_chunk(1, 32);
    store_chunk(0, 0);
    __syncthreads();

#pragma unroll 1
    for (int ch = 0; ch < NCH; ch++) {
        if (ch + 2 < NCH) load_chunk(ch & 1, (ch + 2) * 32);
        compute(ch & 1);
        if (ch + 1 < NCH) {
            store_chunk((ch + 1) & 1, (ch + 1) & 1);
            __syncthreads();
        }
    }

    // epilogue (R4-verified layout)
    int g = lane >> 2, tq = lane & 3;
#pragma unroll
    for (int half = 0; half < 2; half++) {
        int m = wm * 16 + g + half * 8;
        if (m >= mcnt) continue;
        float w = (EPI == 1) ? s_wt[m] : 0.0f;
        float* op = O + (size_t)s_orow[m] * ostride + n0 + wn * 32 + 2 * tq;
#pragma unroll
        for (int nt = 0; nt < 4; nt++) {
            float v0, v1;
            if (EPI == 0) {
                v0 = silu(acc[0][nt][half * 2])     * acc[1][nt][half * 2];
                v1 = silu(acc[0][nt][half * 2 + 1]) * acc[1][nt][half * 2 + 1];
            } else if (EPI == 1) {
                v0 = acc[0][nt][half * 2] * w;
                v1 = acc[0][nt][half * 2 + 1] * w;
            } else {
                v0 = acc[0][nt][half * 2];
                v1 = acc[0][nt][half * 2 + 1];
            }
            *(float2*)&op[nt * 8] = make_float2(v0, v1);
        }
    }
}

// ---- K1: sharedUp (256 blocks) + routed stageA (4096 blocks) ----
#define K1_SHARED 256
#define K1_TOTAL (K1_SHARED + 8 * 64 * 8)
#define K1_SMEM (10240 + 40960)
__global__ __launch_bounds__(128) void k1_kernel(
    const float* __restrict__ x, const float* __restrict__ w1,
    const float* __restrict__ w3, const float* __restrict__ wsg,
    const float* __restrict__ wsu)
{
    extern __shared__ char dyn[];
    int id = blockIdx.x;
    if (id < K1_SHARED) {
        // sact = silu(x @ wsg^T) * (x @ wsu^T)
        gemm_body<1024, true, 0, false, false, 0, 3>(
            id & 31, id >> 5, 0, x, wsg, wsu, nullptr, SI, 0, dyn);
    } else {
        int rid = id - K1_SHARED;
        // act = silu(x_e @ w1^T) * (x_e @ w3^T)  [gather tokens]
        gemm_body<1024, true, 0, true, true, 0, 1>(
            rid & 7, (rid >> 3) & 63, rid >> 9, x, w1, w3, nullptr,
            IDIM, (long)IDIM * H, dyn);
    }
}

// ---- K2: sharedDown (128 blocks) + routed stageB (8192 blocks) ----
#define K2_SHARED 128
#define K2_TOTAL (K2_SHARED + 16 * 64 * 8)
#define K2_SMEM (10240 + 20480)
__global__ __launch_bounds__(128) void k2_kernel(
    const float* __restrict__ w2, const float* __restrict__ wsd,
    float* __restrict__ out)
{
    extern __shared__ char dyn[];
    int id = blockIdx.x;
    if (id < K2_SHARED) {
        // out = sact @ wsd^T
        gemm_body<2048, false, 2, false, false, 2, 0>(
            id & 15, id >> 4, 0, nullptr, wsd, wsd, out, H, 0, dyn);
    } else {
        int rid = id - K2_SHARED;
        // eo = (act_e @ w2^T) * cw  [gather slots]
        gemm_body<512, false, 1, true, false, 1, 2>(
            rid & 15, (rid >> 4) & 63, rid >> 10, nullptr, w2, w2, nullptr,
            H, (long)H * IDIM, dyn);
    }
}

// ---- combine: out += sum of the 6 weighted expert outputs per token ----
__global__ void combine_kernel(float* __restrict__ out) {
    int idx = blockIdx.x * 256 + threadIdx.x;
    int t = idx >> 10;
    int h = idx & 1023;
    float s = out[idx];
#pragma unroll
    for (int k = 0; k < TOPK; k++)
        s += g_eo[((size_t)(t * TOPK + k) << 10) + h];
    out[idx] = s;
}

// ---------------- launch ----------------
extern "C" void kernel_launch(void* const* d_in, const int* in_sizes, int n_in,
                              void* d_out, int out_size) {
    const float* x     = (const float*)d_in[0];
    const float* gw    = (const float*)d_in[1];
    const float* ebias = (const float*)d_in[2];
    const float* w1    = (const float*)d_in[3];
    const float* w3    = (const float*)d_in[4];
    const float* w2    = (const float*)d_in[5];
    const float* wsg   = (const float*)d_in[6];
    const float* wsu   = (const float*)d_in[7];
    const float* wsd   = (const float*)d_in[8];
    float* out = (float*)d_out;

    cudaFuncSetAttribute(k1_kernel, cudaFuncAttributeMaxDynamicSharedMemorySize, K1_SMEM);
    cudaFuncSetAttribute(k2_kernel, cudaFuncAttributeMaxDynamicSharedMemorySize, K2_SMEM);

    init_kernel<<<1, 64>>>();
    gate_routing_kernel<<<T, 256>>>(x, gw, ebias);
    k1_kernel<<<K1_TOTAL, 128, K1_SMEM>>>(x, w1, w3, wsg, wsu);
    k2_kernel<<<K2_TOTAL, 128, K2_SMEM>>>(w2, wsd, out);
    combine_kernel<<<(T * H) / 256, 256>>>(out);
}

// round 13
// speedup vs baseline: 1.4103x; 1.4066x over previous
#include <cuda_runtime.h>
#include <cuda_bf16.h>
#include <cstdint>

#define T 256
#define H 1024
#define E 64
#define IDIM 512
#define SI 2048
#define TOPK 6

// ---------------- device scratch ----------------
__device__ int   g_cnt[E];
__device__ int   g_slot[E * T];
__device__ int   g_tok[E * T];
__device__ float g_wt[E * T];
__device__ float g_act[T * TOPK * IDIM];   // 3 MB
__device__ float g_eo[T * TOPK * H];       // 6 MB
__device__ float g_sact[T * SI];           // 2 MB

__device__ __forceinline__ float silu(float v) { return v / (1.0f + expf(-v)); }

// ---------------- init ----------------
__global__ void init_kernel() {
    if (threadIdx.x < E) g_cnt[threadIdx.x] = 0;
}

// ---------------- gate + routing: one block per token ----------------
__global__ void gate_routing_kernel(const float* __restrict__ x,
                                    const float* __restrict__ gw,
                                    const float* __restrict__ ebias) {
    __shared__ float xs[H];
    __shared__ float part[256];
    __shared__ float logits[E];
    int t = blockIdx.x, tid = threadIdx.x;

    ((float4*)xs)[tid] = ((const float4*)(x + (size_t)t * H))[tid];
    __syncthreads();

    int e = tid >> 2, q = tid & 3;
    const float* gr = gw + (size_t)e * H + q * 256;
    const float* xr = xs + q * 256;
    float s = 0.0f;
#pragma unroll 8
    for (int k = 0; k < 256; k += 4) {
        float4 g = *(const float4*)(gr + k);
        float4 xv = *(const float4*)(xr + k);
        s += g.x * xv.x + g.y * xv.y + g.z * xv.z + g.w * xv.w;
    }
    part[tid] = s;
    __syncthreads();
    if (tid < E) logits[tid] = part[tid * 4] + part[tid * 4 + 1] + part[tid * 4 + 2] + part[tid * 4 + 3];
    __syncthreads();

    if (tid == 0) {
        float sc[E], swb[E];
        for (int i = 0; i < E; i++) {
            float l = logits[i];
            sc[i] = 1.0f / (1.0f + expf(-l));
            swb[i] = sc[i] + ebias[i];
        }
        float gs[8];
        for (int g = 0; g < 8; g++) {
            float m1 = -1e30f, m2 = -1e30f;
            for (int j = 0; j < 8; j++) {
                float v = swb[g * 8 + j];
                if (v > m1) { m2 = m1; m1 = v; }
                else if (v > m2) { m2 = v; }
            }
            gs[g] = m1 + m2;
        }
        bool gsel[8];
        for (int g = 0; g < 8; g++) gsel[g] = false;
        for (int r = 0; r < 4; r++) {
            int best = 0; float bv = -1e30f;
            for (int g = 0; g < 8; g++)
                if (!gsel[g] && gs[g] > bv) { bv = gs[g]; best = g; }
            gsel[best] = true;
        }
        bool picked[E];
        for (int i = 0; i < E; i++) picked[i] = false;
        int idx[TOPK];
        float wsum = 0.0f;
        for (int r = 0; r < TOPK; r++) {
            int best = 0; float bv = -1e30f;
            for (int i = 0; i < E; i++) {
                if (picked[i]) continue;
                float v = gsel[i >> 3] ? swb[i] : 0.0f;
                if (v > bv) { bv = v; best = i; }
            }
            picked[best] = true;
            idx[r] = best;
            wsum += sc[best];
        }
        float inv = 2.5f / (wsum + 1e-20f);
        for (int r = 0; r < TOPK; r++) {
            int ee = idx[r];
            int pos = atomicAdd(&g_cnt[ee], 1);
            g_slot[ee * T + pos] = t * TOPK + r;
            g_tok[ee * T + pos] = t;
            g_wt[ee * T + pos] = sc[ee] * inv;
        }
    }
}

// ====== bf16-split MMA GEMM: champion schema, 2 warp-quads, N128 ======
// C[M=32, N=128] = A[32, KD] * B[N, KD]^T. fp32 -> bf16 hi/lo in smem,
// 3-term MMA (hh + hl + lh). 256 threads = 2 quads; each quad = the
// verified 4-warp (wm, wn) m16 x n32 layout over its own N64 half with its
// own smem B buffers. A tile staged once, shared by both quads.

__device__ __forceinline__ void ldsm4(unsigned r[4], unsigned addr) {
    asm volatile("ldmatrix.sync.aligned.m8n8.x4.shared.b16 {%0,%1,%2,%3}, [%4];"
        : "=r"(r[0]), "=r"(r[1]), "=r"(r[2]), "=r"(r[3]) : "r"(addr));
}

__device__ __forceinline__ void mma_bf16(float c[4], const unsigned a[4],
                                         unsigned b0, unsigned b1) {
    asm("mma.sync.aligned.m16n8k16.row.col.f32.bf16.bf16.f32 "
        "{%0,%1,%2,%3}, {%4,%5,%6,%7}, {%8,%9}, {%0,%1,%2,%3};"
        : "+f"(c[0]), "+f"(c[1]), "+f"(c[2]), "+f"(c[3])
        : "r"(a[0]), "r"(a[1]), "r"(a[2]), "r"(a[3]), "r"(b0), "r"(b1));
}

// champion cvt_store: float4 -> 4 bf16 hi + 4 bf16 lo (bfloat162 stores)
__device__ __forceinline__ void cvt_store(float4 v, __nv_bfloat16* hi, __nv_bfloat16* lo) {
    __nv_bfloat162 h01 = __floats2bfloat162_rn(v.x, v.y);
    __nv_bfloat162 h23 = __floats2bfloat162_rn(v.z, v.w);
    float2 f01 = __bfloat1622float2(h01);
    float2 f23 = __bfloat1622float2(h23);
    *(__nv_bfloat162*)hi       = h01;
    *(__nv_bfloat162*)(hi + 2) = h23;
    *(__nv_bfloat162*)lo       = __floats2bfloat162_rn(v.x - f01.x, v.y - f01.y);
    *(__nv_bfloat162*)(lo + 2) = __floats2bfloat162_rn(v.z - f23.x, v.w - f23.y);
}

// smem element layout (bf16 counts):
//   sA: [2 buf][2 plane][32*40]
//   sB: [quad][2 buf][NB][2 plane][64*40]
#define APLANE 1280
#define BPLANE 2560

// EPI: 0 = silu(acc0)*acc1   1 = acc0 * combine_weight   2 = plain acc0
template<int KD, bool TWOB, int EPI, bool GATHER, bool ATOK, int ASRC, int ODST>
__device__ __forceinline__ void gemm_body(
    int bx, int by, int bz,
    const float* __restrict__ Ain, const float* __restrict__ B1in,
    const float* __restrict__ B2in, float* __restrict__ Oout,
    int ostride, long estrideB, char* dynsmem)
{
    constexpr int NB = TWOB ? 2 : 1;
    constexpr int NCH = KD / 32;
    constexpr int QB = 2 * NB * 2 * BPLANE;   // bf16 elems per quad B region

    const float* A = (ASRC == 0) ? Ain : (ASRC == 1) ? (const float*)g_act : (const float*)g_sact;
    float* O = (ODST == 0) ? Oout : (ODST == 1) ? g_act : (ODST == 2) ? g_eo : g_sact;

    int tid = threadIdx.x, lane = tid & 31, wid = tid >> 5;
    int quad = wid >> 2;                 // 0 or 1: which N64 half
    int wq = wid & 3;                    // warp within quad
    int wm = wq & 1, wn = wq >> 1;
    int n0 = bx * 128 + quad * 64;

    __nv_bfloat16* sA = (__nv_bfloat16*)dynsmem;
    __nv_bfloat16* sB = sA + 2 * 2 * APLANE;
    __nv_bfloat16* sBq = sB + quad * QB;

    __shared__ int s_row[32];
    __shared__ int s_orow[32];
    __shared__ float s_wt[32];

    int mcnt = 32;
    const float* Bp[NB];
    if (GATHER) {
        int e = by;
        int n = g_cnt[e];
        int m0 = bz * 32;
        if (m0 >= n) return;
        mcnt = min(32, n - m0);
        if (tid < 32) {
            bool v = tid < mcnt;
            int idx = e * T + m0 + tid;
            s_row[tid]  = v ? (ATOK ? g_tok[idx] : g_slot[idx]) : -1;
            s_orow[tid] = v ? g_slot[idx] : 0;
            s_wt[tid]   = v ? g_wt[idx] : 0.0f;
        }
        Bp[0] = B1in + (size_t)e * estrideB + (size_t)n0 * KD;
        if (TWOB) Bp[1] = B2in + (size_t)e * estrideB + (size_t)n0 * KD;
    } else {
        int m0 = by * 32;
        if (tid < 32) { s_row[tid] = m0 + tid; s_orow[tid] = m0 + tid; }
        Bp[0] = B1in + (size_t)n0 * KD;
        if (TWOB) Bp[1] = B2in + (size_t)n0 * KD;
    }
    __syncthreads();

    // staging maps (champion geometry, scaled to 256 threads)
    // A: 256 threads stage 32 rows x 8 float4-cols, one float4 each
    int ar = tid >> 3, ac = tid & 7;
    // B: each quad's 128 threads stage its 64 rows x 8 float4-cols, 4 each
    int qtid = tid & 127;
    int br = qtid >> 1, bc = (qtid & 1) * 4;
    long aoff = (long)s_row[ar];

    float4 pa;
    float4 pb[NB][4];

    auto load_chunk = [&](int kt) {
        if (!GATHER || aoff >= 0)
            pa = *(const float4*)&A[(size_t)aoff * KD + kt + ac * 4];
        else
            pa = make_float4(0.f, 0.f, 0.f, 0.f);
#pragma unroll
        for (int m = 0; m < NB; m++)
#pragma unroll
            for (int i = 0; i < 4; i++)
                pb[m][i] = *(const float4*)&Bp[m][(size_t)br * KD + kt + (bc + i) * 4];
    };

    auto store_chunk = [&](int buf) {
        // A staged by all threads (both quads write disjoint float4s)
        cvt_store(pa,
            &sA[(buf * 2 + 0) * APLANE + ar * 40 + ac * 4],
            &sA[(buf * 2 + 1) * APLANE + ar * 40 + ac * 4]);
#pragma unroll
        for (int m = 0; m < NB; m++)
#pragma unroll
            for (int i = 0; i < 4; i++)
                cvt_store(pb[m][i],
                    &sBq[((buf * NB + m) * 2 + 0) * BPLANE + br * 40 + (bc + i) * 4],
                    &sBq[((buf * NB + m) * 2 + 1) * BPLANE + br * 40 + (bc + i) * 4]);
    };

    float acc[NB][4][4];
#pragma unroll
    for (int m = 0; m < NB; m++)
#pragma unroll
        for (int nt = 0; nt < 4; nt++)
#pragma unroll
            for (int j = 0; j < 4; j++) acc[m][nt][j] = 0.0f;

    unsigned aSm = (unsigned)__cvta_generic_to_shared(sA);
    unsigned bSm = (unsigned)__cvta_generic_to_shared(sBq);
    int arow_off = ((wm * 16 + (lane & 15)) * 40 + ((lane >> 4) & 1) * 8) * 2;
    int brow_base = wn * 32 + (lane & 7) + ((lane & 16) >> 1);
    int bcol_off = (lane & 8);

    auto compute = [&](int buf) {
        unsigned aHi = aSm + (unsigned)(buf * 2 * APLANE * 2);
        unsigned aLo = aHi + APLANE * 2;
#pragma unroll
        for (int s = 0; s < 2; s++) {
            unsigned ah[4], al[4];
            ldsm4(ah, aHi + arow_off + s * 32);
            ldsm4(al, aLo + arow_off + s * 32);
#pragma unroll
            for (int m = 0; m < NB; m++) {
                unsigned bHi = bSm + (unsigned)(((buf * NB + m) * 2) * BPLANE * 2);
                unsigned bLo = bHi + BPLANE * 2;
                int o0 = (brow_base * 40 + s * 16 + bcol_off) * 2;
                int o1 = ((brow_base + 16) * 40 + s * 16 + bcol_off) * 2;
                unsigned bh[8], bl[8];
                ldsm4(bh, bHi + o0); ldsm4(bh + 4, bHi + o1);
                ldsm4(bl, bLo + o0); ldsm4(bl + 4, bLo + o1);
#pragma unroll
                for (int nt = 0; nt < 4; nt++) {
                    mma_bf16(acc[m][nt], ah, bh[nt * 2], bh[nt * 2 + 1]);
                    mma_bf16(acc[m][nt], ah, bl[nt * 2], bl[nt * 2 + 1]);
                    mma_bf16(acc[m][nt], al, bh[nt * 2], bh[nt * 2 + 1]);
                }
            }
        }
    };

    // champion pipeline: double-buffered smem, 1 barrier per chunk
    load_chunk(0);
    store_chunk(0);
    __syncthreads();
#pragma unroll 1
    for (int ch = 0; ch < NCH; ch++) {
        if (ch + 1 < NCH) load_chunk((ch + 1) * 32);
        compute(ch & 1);
        if (ch + 1 < NCH) {
            store_chunk((ch + 1) & 1);
            __syncthreads();
        }
    }

    // epilogue (champion layout)
    int g = lane >> 2, tq = lane & 3;
#pragma unroll
    for (int half = 0; half < 2; half++) {
        int m = wm * 16 + g + half * 8;
        if (m >= mcnt) continue;
        float w = (EPI == 1) ? s_wt[m] : 0.0f;
        float* op = O + (size_t)s_orow[m] * ostride + n0 + wn * 32 + 2 * tq;
#pragma unroll
        for (int nt = 0; nt < 4; nt++) {
            float v0, v1;
            if (EPI == 0) {
                v0 = silu(acc[0][nt][half * 2])     * acc[1][nt][half * 2];
                v1 = silu(acc[0][nt][half * 2 + 1]) * acc[1][nt][half * 2 + 1];
            } else if (EPI == 1) {
                v0 = acc[0][nt][half * 2] * w;
                v1 = acc[0][nt][half * 2 + 1] * w;
            } else {
                v0 = acc[0][nt][half * 2];
                v1 = acc[0][nt][half * 2 + 1];
            }
            *(float2*)&op[nt * 8] = make_float2(v0, v1);
        }
    }
}

// ---- K1: sharedUp (128 blocks) + routed stageA (2048 blocks) ----
#define K1_SHARED 128
#define K1_TOTAL (K1_SHARED + 4 * 64 * 8)
#define K1_SMEM (10240 + 2 * 2 * 2 * 2 * BPLANE * 2)    // 10240 + 81920
__global__ __launch_bounds__(256) void k1_kernel(
    const float* __restrict__ x, const float* __restrict__ w1,
    const float* __restrict__ w3, const float* __restrict__ wsg,
    const float* __restrict__ wsu)
{
    extern __shared__ char dyn[];
    int id = blockIdx.x;
    if (id < K1_SHARED) {
        // sact = silu(x @ wsg^T) * (x @ wsu^T)   [16 n-tiles x 8 m-tiles]
        gemm_body<1024, true, 0, false, false, 0, 3>(
            id & 15, id >> 4, 0, x, wsg, wsu, nullptr, SI, 0, dyn);
    } else {
        int rid = id - K1_SHARED;
        // act = silu(x_e @ w1^T) * (x_e @ w3^T)  [gather tokens]
        gemm_body<1024, true, 0, true, true, 0, 1>(
            rid & 3, (rid >> 2) & 63, rid >> 8, x, w1, w3, nullptr,
            IDIM, (long)IDIM * H, dyn);
    }
}

// ---- K2: sharedDown (64 blocks) + routed stageB (4096 blocks) ----
#define K2_SHARED 64
#define K2_TOTAL (K2_SHARED + 8 * 64 * 8)
#define K2_SMEM (10240 + 2 * 2 * 1 * 2 * BPLANE * 2)    // 10240 + 40960
__global__ __launch_bounds__(256) void k2_kernel(
    const float* __restrict__ w2, const float* __restrict__ wsd,
    float* __restrict__ out)
{
    extern __shared__ char dyn[];
    int id = blockIdx.x;
    if (id < K2_SHARED) {
        // out = sact @ wsd^T   [8 n-tiles x 8 m-tiles]
        gemm_body<2048, false, 2, false, false, 2, 0>(
            id & 7, id >> 3, 0, nullptr, wsd, wsd, out, H, 0, dyn);
    } else {
        int rid = id - K2_SHARED;
        // eo = (act_e @ w2^T) * cw  [gather slots]
        gemm_body<512, false, 1, true, false, 1, 2>(
            rid & 7, (rid >> 3) & 63, rid >> 9, nullptr, w2, w2, nullptr,
            H, (long)H * IDIM, dyn);
    }
}

// ---- combine: out += sum of the 6 weighted expert outputs per token ----
__global__ void combine_kernel(float* __restrict__ out) {
    int idx = blockIdx.x * 256 + threadIdx.x;
    int t = idx >> 10;
    int h = idx & 1023;
    float s = out[idx];
#pragma unroll
    for (int k = 0; k < TOPK; k++)
        s += g_eo[((size_t)(t * TOPK + k) << 10) + h];
    out[idx] = s;
}

// ---------------- launch ----------------
extern "C" void kernel_launch(void* const* d_in, const int* in_sizes, int n_in,
                              void* d_out, int out_size) {
    const float* x     = (const float*)d_in[0];
    const float* gw    = (const float*)d_in[1];
    const float* ebias = (const float*)d_in[2];
    const float* w1    = (const float*)d_in[3];
    const float* w3    = (const float*)d_in[4];
    const float* w2    = (const float*)d_in[5];
    const float* wsg   = (const float*)d_in[6];
    const float* wsu   = (const float*)d_in[7];
    const float* wsd   = (const float*)d_in[8];
    float* out = (float*)d_out;

    cudaFuncSetAttribute(k1_kernel, cudaFuncAttributeMaxDynamicSharedMemorySize, K1_SMEM);
    cudaFuncSetAttribute(k2_kernel, cudaFuncAttributeMaxDynamicSharedMemorySize, K2_SMEM);

    init_kernel<<<1, 64>>>();
    gate_routing_kernel<<<T, 256>>>(x, gw, ebias);
    k1_kernel<<<K1_TOTAL, 256, K1_SMEM>>>(x, w1, w3, wsg, wsu);
    k2_kernel<<<K2_TOTAL, 256, K2_SMEM>>>(w2, wsd, out);
    combine_kernel<<<(T * H) / 256, 256>>>(out);
}

// round 14
// speedup vs baseline: 1.9431x; 1.3778x over previous
#include <cuda_runtime.h>
#include <cuda_bf16.h>

#define T 256
#define H 1024
#define E 64
#define IDIM 512
#define SI 2048
#define TOPK 6

// ---------------- device scratch ----------------
__device__ int   g_cnt[E];
__device__ int   g_slot[E * T];
__device__ int   g_tok[E * T];
__device__ float g_wt[E * T];
__device__ float g_act[T * TOPK * IDIM];   // 3 MB
__device__ float g_eo[T * TOPK * H];       // 6 MB
__device__ float g_sact[T * SI];           // 2 MB

__device__ __forceinline__ float silu(float v) { return v / (1.0f + expf(-v)); }

// ---------------- init ----------------
__global__ void init_kernel() {
    if (threadIdx.x < E) g_cnt[threadIdx.x] = 0;
}

// ---------------- gate + routing: one block per token ----------------
__global__ void gate_routing_kernel(const float* __restrict__ x,
                                    const float* __restrict__ gw,
                                    const float* __restrict__ ebias) {
    __shared__ float xs[H];
    __shared__ float part[256];
    __shared__ float logits[E];
    int t = blockIdx.x, tid = threadIdx.x;

    ((float4*)xs)[tid] = ((const float4*)(x + (size_t)t * H))[tid];
    __syncthreads();

    int e = tid >> 2, q = tid & 3;
    const float* gr = gw + (size_t)e * H + q * 256;
    const float* xr = xs + q * 256;
    float s = 0.0f;
#pragma unroll 8
    for (int k = 0; k < 256; k += 4) {
        float4 g = *(const float4*)(gr + k);
        float4 xv = *(const float4*)(xr + k);
        s += g.x * xv.x + g.y * xv.y + g.z * xv.z + g.w * xv.w;
    }
    part[tid] = s;
    __syncthreads();
    if (tid < E) logits[tid] = part[tid * 4] + part[tid * 4 + 1] + part[tid * 4 + 2] + part[tid * 4 + 3];
    __syncthreads();

    if (tid == 0) {
        float sc[E], swb[E];
        for (int i = 0; i < E; i++) {
            float l = logits[i];
            sc[i] = 1.0f / (1.0f + expf(-l));
            swb[i] = sc[i] + ebias[i];
        }
        float gs[8];
        for (int g = 0; g < 8; g++) {
            float m1 = -1e30f, m2 = -1e30f;
            for (int j = 0; j < 8; j++) {
                float v = swb[g * 8 + j];
                if (v > m1) { m2 = m1; m1 = v; }
                else if (v > m2) { m2 = v; }
            }
            gs[g] = m1 + m2;
        }
        bool gsel[8];
        for (int g = 0; g < 8; g++) gsel[g] = false;
        for (int r = 0; r < 4; r++) {
            int best = 0; float bv = -1e30f;
            for (int g = 0; g < 8; g++)
                if (!gsel[g] && gs[g] > bv) { bv = gs[g]; best = g; }
            gsel[best] = true;
        }
        bool picked[E];
        for (int i = 0; i < E; i++) picked[i] = false;
        int idx[TOPK];
        float wsum = 0.0f;
        for (int r = 0; r < TOPK; r++) {
            int best = 0; float bv = -1e30f;
            for (int i = 0; i < E; i++) {
                if (picked[i]) continue;
                float v = gsel[i >> 3] ? swb[i] : 0.0f;
                if (v > bv) { bv = v; best = i; }
            }
            picked[best] = true;
            idx[r] = best;
            wsum += sc[best];
        }
        float inv = 2.5f / (wsum + 1e-20f);
        for (int r = 0; r < TOPK; r++) {
            int ee = idx[r];
            int pos = atomicAdd(&g_cnt[ee], 1);
            g_slot[ee * T + pos] = t * TOPK + r;
            g_tok[ee * T + pos] = t;
            g_wt[ee * T + pos] = sc[ee] * inv;
        }
    }
}

// ================= unified bf16-split MMA GEMM (champion + coalesced LDG) ===
// C[M=32, N=64] = A[32, KD] * B[N, KD]^T, fp32 in HBM, converted to bf16
// hi/lo in-register, 3-term MMA (hi*hi + hi*lo + lo*hi) for fp32 accuracy.
// 128 threads = 4 warps: warp (wm, wn) handles m16 x n32.
// Staging map: 8 consecutive lanes cover one row's 128 contiguous bytes
// (1 L1 line per 8 lanes per LDG.128 -> 4 wavefronts/instr, optimal).

__device__ __forceinline__ void ldsm4(unsigned r[4], unsigned addr) {
    asm volatile("ldmatrix.sync.aligned.m8n8.x4.shared.b16 {%0,%1,%2,%3}, [%4];"
        : "=r"(r[0]), "=r"(r[1]), "=r"(r[2]), "=r"(r[3]) : "r"(addr));
}

__device__ __forceinline__ void mma_bf16(float c[4], const unsigned a[4],
                                         unsigned b0, unsigned b1) {
    asm("mma.sync.aligned.m16n8k16.row.col.f32.bf16.bf16.f32 "
        "{%0,%1,%2,%3}, {%4,%5,%6,%7}, {%8,%9}, {%0,%1,%2,%3};"
        : "+f"(c[0]), "+f"(c[1]), "+f"(c[2]), "+f"(c[3])
        : "r"(a[0]), "r"(a[1]), "r"(a[2]), "r"(a[3]), "r"(b0), "r"(b1));
}

__device__ __forceinline__ void cvt_store(float4 v, __nv_bfloat16* hi, __nv_bfloat16* lo) {
    __nv_bfloat162 h01 = __floats2bfloat162_rn(v.x, v.y);
    __nv_bfloat162 h23 = __floats2bfloat162_rn(v.z, v.w);
    float2 f01 = __bfloat1622float2(h01);
    float2 f23 = __bfloat1622float2(h23);
    *(__nv_bfloat162*)hi       = h01;
    *(__nv_bfloat162*)(hi + 2) = h23;
    *(__nv_bfloat162*)lo       = __floats2bfloat162_rn(v.x - f01.x, v.y - f01.y);
    *(__nv_bfloat162*)(lo + 2) = __floats2bfloat162_rn(v.z - f23.x, v.w - f23.y);
}

// smem element layout (bf16 counts):
//   sA: [2 buf][2 plane][32*40]
//   sB: [2 buf][NB][2 plane][64*40]
#define APLANE 1280
#define BPLANE 2560

// EPI: 0 = silu(acc0)*acc1   1 = acc0 * combine_weight   2 = plain acc0
template<int KD, bool TWOB, int EPI, bool GATHER, bool ATOK, int ASRC, int ODST>
__device__ __forceinline__ void gemm_body(
    int bx, int by, int bz,
    const float* __restrict__ Ain, const float* __restrict__ B1in,
    const float* __restrict__ B2in, float* __restrict__ Oout,
    int ostride, long estrideB, char* dynsmem)
{
    constexpr int NB = TWOB ? 2 : 1;
    constexpr int NCH = KD / 32;

    const float* A = (ASRC == 0) ? Ain : (ASRC == 1) ? (const float*)g_act : (const float*)g_sact;
    float* O = (ODST == 0) ? Oout : (ODST == 1) ? g_act : (ODST == 2) ? g_eo : g_sact;

    int tid = threadIdx.x, lane = tid & 31, wid = tid >> 5;
    int wm = wid & 1, wn = wid >> 1;
    int n0 = bx * 64;

    __nv_bfloat16* sA = (__nv_bfloat16*)dynsmem;
    __nv_bfloat16* sB = sA + 2 * 2 * APLANE;

    __shared__ int s_row[32];
    __shared__ int s_orow[32];
    __shared__ float s_wt[32];

    int mcnt = 32;
    const float* Bp[NB];
    if (GATHER) {
        int e = by;
        int n = g_cnt[e];
        int m0 = bz * 32;
        if (m0 >= n) return;
        mcnt = min(32, n - m0);
        if (tid < 32) {
            bool v = tid < mcnt;
            int idx = e * T + m0 + tid;
            s_row[tid]  = v ? (ATOK ? g_tok[idx] : g_slot[idx]) : -1;
            s_orow[tid] = v ? g_slot[idx] : 0;
            s_wt[tid]   = v ? g_wt[idx] : 0.0f;
        }
        Bp[0] = B1in + (size_t)e * estrideB + (size_t)n0 * KD;
        if (TWOB) Bp[1] = B2in + (size_t)e * estrideB + (size_t)n0 * KD;
    } else {
        int m0 = by * 32;
        if (tid < 32) { s_row[tid] = m0 + tid; s_orow[tid] = m0 + tid; }
        Bp[0] = B1in + (size_t)n0 * KD;
        if (TWOB) Bp[1] = B2in + (size_t)n0 * KD;
    }
    __syncthreads();

    // coalesced staging map: 8 lanes cover one row's 128B segment.
    // A: 32 rows x 8 float4-cols, thread handles rows (tid>>3, +16), col tid&7
    // B: 64 rows x 8 float4-cols, thread handles rows (tid>>3 +16i), col tid&7
    int srow = tid >> 3, scol = tid & 7;
    long aoff0 = (long)s_row[srow];
    long aoff1 = (long)s_row[srow + 16];

    float4 pa[2];
    float4 pb[NB][4];

    auto load_chunk = [&](int kt) {
        if (!GATHER || aoff0 >= 0)
            pa[0] = *(const float4*)&A[(size_t)aoff0 * KD + kt + scol * 4];
        else
            pa[0] = make_float4(0.f, 0.f, 0.f, 0.f);
        if (!GATHER || aoff1 >= 0)
            pa[1] = *(const float4*)&A[(size_t)aoff1 * KD + kt + scol * 4];
        else
            pa[1] = make_float4(0.f, 0.f, 0.f, 0.f);
#pragma unroll
        for (int m = 0; m < NB; m++)
#pragma unroll
            for (int i = 0; i < 4; i++)
                pb[m][i] = *(const float4*)&Bp[m][(size_t)(srow + 16 * i) * KD + kt + scol * 4];
    };

    auto store_chunk = [&]() {
#pragma unroll
        for (int i = 0; i < 2; i++)
            cvt_store(pa[i],
                &sA[0 * APLANE + (srow + 16 * i) * 40 + scol * 4],
                &sA[1 * APLANE + (srow + 16 * i) * 40 + scol * 4]);
#pragma unroll
        for (int m = 0; m < NB; m++)
#pragma unroll
            for (int i = 0; i < 4; i++)
                cvt_store(pb[m][i],
                    &sB[(m * 2 + 0) * BPLANE + (srow + 16 * i) * 40 + scol * 4],
                    &sB[(m * 2 + 1) * BPLANE + (srow + 16 * i) * 40 + scol * 4]);
    };

    auto store_chunk_buf = [&](int buf) {
#pragma unroll
        for (int i = 0; i < 2; i++)
            cvt_store(pa[i],
                &sA[(buf * 2 + 0) * APLANE + (srow + 16 * i) * 40 + scol * 4],
                &sA[(buf * 2 + 1) * APLANE + (srow + 16 * i) * 40 + scol * 4]);
#pragma unroll
        for (int m = 0; m < NB; m++)
#pragma unroll
            for (int i = 0; i < 4; i++)
                cvt_store(pb[m][i],
                    &sB[((buf * NB + m) * 2 + 0) * BPLANE + (srow + 16 * i) * 40 + scol * 4],
                    &sB[((buf * NB + m) * 2 + 1) * BPLANE + (srow + 16 * i) * 40 + scol * 4]);
    };
    (void)store_chunk;

    float acc[NB][4][4];
#pragma unroll
    for (int m = 0; m < NB; m++)
#pragma unroll
        for (int nt = 0; nt < 4; nt++)
#pragma unroll
            for (int j = 0; j < 4; j++) acc[m][nt][j] = 0.0f;

    unsigned aSm = (unsigned)__cvta_generic_to_shared(sA);
    unsigned bSm = (unsigned)__cvta_generic_to_shared(sB);
    int arow_off = ((wm * 16 + (lane & 15)) * 40 + ((lane >> 4) & 1) * 8) * 2;
    int brow_base = wn * 32 + (lane & 7) + ((lane & 16) >> 1);
    int bcol_off = (lane & 8);

    auto compute = [&](int buf) {
        unsigned aHi = aSm + (unsigned)(buf * 2 * APLANE * 2);
        unsigned aLo = aHi + APLANE * 2;
#pragma unroll
        for (int s = 0; s < 2; s++) {
            unsigned ah[4], al[4];
            ldsm4(ah, aHi + arow_off + s * 32);
            ldsm4(al, aLo + arow_off + s * 32);
#pragma unroll
            for (int m = 0; m < NB; m++) {
                unsigned bHi = bSm + (unsigned)(((buf * NB + m) * 2) * BPLANE * 2);
                unsigned bLo = bHi + BPLANE * 2;
                int o0 = (brow_base * 40 + s * 16 + bcol_off) * 2;
                int o1 = ((brow_base + 16) * 40 + s * 16 + bcol_off) * 2;
                unsigned bh[8], bl[8];
                ldsm4(bh, bHi + o0); ldsm4(bh + 4, bHi + o1);
                ldsm4(bl, bLo + o0); ldsm4(bl + 4, bLo + o1);
#pragma unroll
                for (int nt = 0; nt < 4; nt++) {
                    mma_bf16(acc[m][nt], ah, bh[nt * 2], bh[nt * 2 + 1]);
                    mma_bf16(acc[m][nt], ah, bl[nt * 2], bl[nt * 2 + 1]);
                    mma_bf16(acc[m][nt], al, bh[nt * 2], bh[nt * 2 + 1]);
                }
            }
        }
    };

    // champion pipeline: double-buffered smem, 1 barrier per chunk
    load_chunk(0);
    store_chunk_buf(0);
    __syncthreads();
#pragma unroll 1
    for (int ch = 0; ch < NCH; ch++) {
        if (ch + 1 < NCH) load_chunk((ch + 1) * 32);
        compute(ch & 1);
        if (ch + 1 < NCH) {
            store_chunk_buf((ch + 1) & 1);
            __syncthreads();
        }
    }

    // epilogue (champion layout)
    int g = lane >> 2, tq = lane & 3;
#pragma unroll
    for (int half = 0; half < 2; half++) {
        int m = wm * 16 + g + half * 8;
        if (m >= mcnt) continue;
        float w = (EPI == 1) ? s_wt[m] : 0.0f;
        float* op = O + (size_t)s_orow[m] * ostride + n0 + wn * 32 + 2 * tq;
#pragma unroll
        for (int nt = 0; nt < 4; nt++) {
            float v0, v1;
            if (EPI == 0) {
                v0 = silu(acc[0][nt][half * 2])     * acc[1][nt][half * 2];
                v1 = silu(acc[0][nt][half * 2 + 1]) * acc[1][nt][half * 2 + 1];
            } else if (EPI == 1) {
                v0 = acc[0][nt][half * 2] * w;
                v1 = acc[0][nt][half * 2 + 1] * w;
            } else {
                v0 = acc[0][nt][half * 2];
                v1 = acc[0][nt][half * 2 + 1];
            }
            *(float2*)&op[nt * 8] = make_float2(v0, v1);
        }
    }
}

// ---- K1: sharedUp (256 blocks) + routed stageA (4096 blocks) ----
#define K1_SHARED 256
#define K1_TOTAL (K1_SHARED + 8 * 64 * 8)
#define K1_SMEM (10240 + 40960)
__global__ __launch_bounds__(128) void k1_kernel(
    const float* __restrict__ x, const float* __restrict__ w1,
    const float* __restrict__ w3, const float* __restrict__ wsg,
    const float* __restrict__ wsu)
{
    extern __shared__ char dyn[];
    int id = blockIdx.x;
    if (id < K1_SHARED) {
        // sact = silu(x @ wsg^T) * (x @ wsu^T)
        gemm_body<1024, true, 0, false, false, 0, 3>(
            id & 31, id >> 5, 0, x, wsg, wsu, nullptr, SI, 0, dyn);
    } else {
        int rid = id - K1_SHARED;
        // act = silu(x_e @ w1^T) * (x_e @ w3^T)  [gather tokens]
        gemm_body<1024, true, 0, true, true, 0, 1>(
            rid & 7, (rid >> 3) & 63, rid >> 9, x, w1, w3, nullptr,
            IDIM, (long)IDIM * H, dyn);
    }
}

// ---- K2: sharedDown (128 blocks) + routed stageB (8192 blocks) ----
#define K2_SHARED 128
#define K2_TOTAL (K2_SHARED + 16 * 64 * 8)
#define K2_SMEM (10240 + 20480)
__global__ __launch_bounds__(128) void k2_kernel(
    const float* __restrict__ w2, const float* __restrict__ wsd,
    float* __restrict__ out)
{
    extern __shared__ char dyn[];
    int id = blockIdx.x;
    if (id < K2_SHARED) {
        // out = sact @ wsd^T
        gemm_body<2048, false, 2, false, false, 2, 0>(
            id & 15, id >> 4, 0, nullptr, wsd, wsd, out, H, 0, dyn);
    } else {
        int rid = id - K2_SHARED;
        // eo = (act_e @ w2^T) * cw  [gather slots]
        gemm_body<512, false, 1, true, false, 1, 2>(
            rid & 15, (rid >> 4) & 63, rid >> 10, nullptr, w2, w2, nullptr,
            H, (long)H * IDIM, dyn);
    }
}

// ---- combine: out += sum of the 6 weighted expert outputs per token ----
__global__ void combine_kernel(float* __restrict__ out) {
    int idx = blockIdx.x * 256 + threadIdx.x;
    int t = idx >> 10;
    int h = idx & 1023;
    float s = out[idx];
#pragma unroll
    for (int k = 0; k < TOPK; k++)
        s += g_eo[((size_t)(t * TOPK + k) << 10) + h];
    out[idx] = s;
}

// ---------------- launch ----------------
extern "C" void kernel_launch(void* const* d_in, const int* in_sizes, int n_in,
                              void* d_out, int out_size) {
    const float* x     = (const float*)d_in[0];
    const float* gw    = (const float*)d_in[1];
    const float* ebias = (const float*)d_in[2];
    const float* w1    = (const float*)d_in[3];
    const float* w3    = (const float*)d_in[4];
    const float* w2    = (const float*)d_in[5];
    const float* wsg   = (const float*)d_in[6];
    const float* wsu   = (const float*)d_in[7];
    const float* wsd   = (const float*)d_in[8];
    float* out = (float*)d_out;

    cudaFuncSetAttribute(k1_kernel, cudaFuncAttributeMaxDynamicSharedMemorySize, K1_SMEM);
    cudaFuncSetAttribute(k2_kernel, cudaFuncAttributeMaxDynamicSharedMemorySize, K2_SMEM);

    init_kernel<<<1, 64>>>();
    gate_routing_kernel<<<T, 256>>>(x, gw, ebias);
    k1_kernel<<<K1_TOTAL, 128, K1_SMEM>>>(x, w1, w3, wsg, wsu);
    k2_kernel<<<K2_TOTAL, 128, K2_SMEM>>>(w2, wsd, out);
    combine_kernel<<<(T * H) / 256, 256>>>(out);
}